// round 10
// baseline (speedup 1.0000x reference)
#include <cuda_runtime.h>
#include <cuda_fp16.h>
#include <cstdint>

#define NN 65536
#define HH 128
#define EE 524288

// ---------------- static scratch ----------------
__device__ int    g_deg[3][NN];
__device__ int    g_rowptr[3][NN + 1];
__device__ int    g_cursor[3][NN];
__device__ int    g_csum[3][256];
__device__ int    g_col[3][EE];
__device__ __half g_h16[3][NN * HH];   // 0: A = pf@Wr1^T, 1: B = rf@Wr2^T, 2: C = rf@Wp^T
__device__ __half g_rf16[NN * HH];
__device__ __half g_pf16[NN * HH];
__device__ __half g_wr16[HH * 256];
__device__ __half g_wp16[HH * HH];

// ---------------- fp16 conversion: feature tables ----------------
__global__ void k_f16(const float* __restrict__ rf, const float* __restrict__ pf) {
    int i = blockIdx.x * blockDim.x + threadIdx.x;   // 8 floats per thread
    const int half_total = NN * HH / 8;
    const float4* src;
    __half* dst;
    int base;
    if (i < half_total) { src = (const float4*)rf; dst = g_rf16; base = i; }
    else                { src = (const float4*)pf; dst = g_pf16; base = i - half_total; }
    float4 v0 = __ldg(src + base * 2);
    float4 v1 = __ldg(src + base * 2 + 1);
    __half2 h[4];
    h[0] = __floats2half2_rn(v0.x, v0.y);
    h[1] = __floats2half2_rn(v0.z, v0.w);
    h[2] = __floats2half2_rn(v1.x, v1.y);
    h[3] = __floats2half2_rn(v1.z, v1.w);
    *(uint4*)(dst + (size_t)base * 8) = *(uint4*)h;
}

// ---------------- fp16 conversion: weights ----------------
__global__ void k_w16(const float* __restrict__ Wr, const float* __restrict__ Wp) {
    int i = blockIdx.x * blockDim.x + threadIdx.x;
    if (i < 16384) {
        float2 v = __ldg((const float2*)Wr + i);
        *(__half2*)(g_wr16 + i * 2) = __floats2half2_rn(v.x, v.y);
    } else if (i < 24576) {
        int j = i - 16384;
        float2 v = __ldg((const float2*)Wp + j);
        *(__half2*)(g_wp16 + j * 2) = __floats2half2_rn(v.x, v.y);
    }
}

// ---------------- CSR build ----------------
__global__ void k_hist(const int* __restrict__ pass_dst,
                       const int* __restrict__ connect_dst,
                       const int* __restrict__ transfer_dst) {
    int q = blockIdx.x * blockDim.x + threadIdx.x;
    if (q >= 3 * EE / 4) return;
    int r = q / (EE / 4), e4 = q - r * (EE / 4);
    const int* dst = (r == 0) ? pass_dst : (r == 1) ? connect_dst : transfer_dst;
    int4 d = __ldg((const int4*)dst + e4);
    atomicAdd(&g_deg[r][d.x], 1);
    atomicAdd(&g_deg[r][d.y], 1);
    atomicAdd(&g_deg[r][d.z], 1);
    atomicAdd(&g_deg[r][d.w], 1);
}

__global__ void k_scan1() {
    int b = blockIdx.x;
    int r = b >> 8, ch = b & 255;
    int t = threadIdx.x;
    int idx = ch * 256 + t;
    int v = g_deg[r][idx];
    __shared__ int sm[256];
    sm[t] = v;
    __syncthreads();
    #pragma unroll
    for (int off = 1; off < 256; off <<= 1) {
        int u = (t >= off) ? sm[t - off] : 0;
        __syncthreads();
        sm[t] += u;
        __syncthreads();
    }
    g_rowptr[r][idx] = sm[t] - v;
    if (t == 255) g_csum[r][ch] = sm[t];
}

__global__ void k_scan2() {
    int r = blockIdx.x;
    int t = threadIdx.x;
    int v = g_csum[r][t];
    __shared__ int sm[256];
    sm[t] = v;
    __syncthreads();
    #pragma unroll
    for (int off = 1; off < 256; off <<= 1) {
        int u = (t >= off) ? sm[t - off] : 0;
        __syncthreads();
        sm[t] += u;
        __syncthreads();
    }
    g_csum[r][t] = sm[t] - v;
    if (t == 255) g_rowptr[r][NN] = sm[t];
}

__global__ void k_scan3() {
    int i = blockIdx.x * blockDim.x + threadIdx.x;
    if (i >= 3 * NN) return;
    int r = i >> 16, n = i & (NN - 1);
    int val = g_rowptr[r][n] + g_csum[r][n >> 8];
    g_rowptr[r][n] = val;
    g_cursor[r][n] = val;
}

__global__ void k_fill(const int* __restrict__ pass_src, const int* __restrict__ pass_dst,
                       const int* __restrict__ connect_src, const int* __restrict__ connect_dst,
                       const int* __restrict__ transfer_src, const int* __restrict__ transfer_dst) {
    int q = blockIdx.x * blockDim.x + threadIdx.x;
    if (q >= 3 * EE / 4) return;
    int r = q / (EE / 4), e4 = q - r * (EE / 4);
    const int *src, *dst;
    if (r == 0)      { src = pass_src;     dst = pass_dst; }
    else if (r == 1) { src = connect_src;  dst = connect_dst; }
    else             { src = transfer_src; dst = transfer_dst; }
    int4 d = __ldg((const int4*)dst + e4);
    int4 s = __ldg((const int4*)src + e4);
    int p0 = atomicAdd(&g_cursor[r][d.x], 1);
    int p1 = atomicAdd(&g_cursor[r][d.y], 1);
    int p2 = atomicAdd(&g_cursor[r][d.z], 1);
    int p3 = atomicAdd(&g_cursor[r][d.w], 1);
    g_col[r][p0] = s.x;
    g_col[r][p1] = s.y;
    g_col[r][p2] = s.z;
    g_col[r][p3] = s.w;
}

// ---------------- fp16 tensor-core plain GEMM ----------------
__device__ __forceinline__ void mma_f16(float* d, const uint32_t* a, const uint32_t* b) {
    asm volatile(
        "mma.sync.aligned.m16n8k16.row.col.f32.f16.f16.f32 "
        "{%0,%1,%2,%3},{%4,%5,%6,%7},{%8,%9},{%0,%1,%2,%3};"
        : "+f"(d[0]), "+f"(d[1]), "+f"(d[2]), "+f"(d[3])
        : "r"(a[0]), "r"(a[1]), "r"(a[2]), "r"(a[3]), "r"(b[0]), "r"(b[1]));
}

#define KC 64
#define XSH 72

template<int LDW, int WOFF>
__global__ void __launch_bounds__(256, 2) k_gemm_h(const __half* __restrict__ X,
                                                   const __half* __restrict__ W,
                                                   __half* __restrict__ Y) {
    __shared__ __half sX[128 * XSH];
    __shared__ __half sW[128 * XSH];

    const int t = threadIdx.x;
    const int warp = t >> 5, lane = t & 31;
    const int g = lane >> 2, tg = lane & 3;
    const int mw = (warp & 3) * 32;
    const int nw = (warp >> 2) * 64;
    const int row0 = blockIdx.x * 128;

    float acc[2][8][4];
    #pragma unroll
    for (int i = 0; i < 2; i++)
        #pragma unroll
        for (int j = 0; j < 8; j++)
            #pragma unroll
            for (int q = 0; q < 4; q++) acc[i][j][q] = 0.f;

    #pragma unroll
    for (int c = 0; c < HH / KC; c++) {
        __syncthreads();
        #pragma unroll
        for (int it = 0; it < 4; it++) {
            int idx = it * 256 + t;
            int row = idx >> 3, c8 = idx & 7;
            uint4 xv = __ldg((const uint4*)(X + (size_t)(row0 + row) * HH + c * KC) + c8);
            *(uint4*)&sX[row * XSH + c8 * 8] = xv;
            uint4 wv = __ldg((const uint4*)(W + (size_t)row * LDW + WOFF + c * KC) + c8);
            *(uint4*)&sW[row * XSH + c8 * 8] = wv;
        }
        __syncthreads();

        #pragma unroll
        for (int ks = 0; ks < KC / 16; ks++) {
            int k0 = ks * 16;
            uint32_t a[2][4], b[8][2];
            #pragma unroll
            for (int i = 0; i < 2; i++) {
                int r = mw + i * 16 + g;
                a[i][0] = *(const uint32_t*)&sX[r * XSH + k0 + 2 * tg];
                a[i][1] = *(const uint32_t*)&sX[(r + 8) * XSH + k0 + 2 * tg];
                a[i][2] = *(const uint32_t*)&sX[r * XSH + k0 + 8 + 2 * tg];
                a[i][3] = *(const uint32_t*)&sX[(r + 8) * XSH + k0 + 8 + 2 * tg];
            }
            #pragma unroll
            for (int j = 0; j < 8; j++) {
                int n = nw + j * 8 + g;
                b[j][0] = *(const uint32_t*)&sW[n * XSH + k0 + 2 * tg];
                b[j][1] = *(const uint32_t*)&sW[n * XSH + k0 + 8 + 2 * tg];
            }
            #pragma unroll
            for (int i = 0; i < 2; i++)
                #pragma unroll
                for (int j = 0; j < 8; j++)
                    mma_f16(acc[i][j], a[i], b[j]);
        }
    }

    #pragma unroll
    for (int j = 0; j < 8; j++) {
        int col = nw + j * 8 + 2 * tg;
        #pragma unroll
        for (int i = 0; i < 2; i++) {
            int ra = row0 + mw + i * 16 + g;
            *(__half2*)(Y + (size_t)ra * HH + col)       = __floats2half2_rn(acc[i][j][0], acc[i][j][1]);
            *(__half2*)(Y + (size_t)(ra + 8) * HH + col) = __floats2half2_rn(acc[i][j][2], acc[i][j][3]);
        }
    }
}

// ---------------- combined fused gather + epilogue ----------------
#define ACCP(P) { float2 f; \
    f = __half22float2((P)[0]); a0.x += f.x; a0.y += f.y; \
    f = __half22float2((P)[1]); a1.x += f.x; a1.y += f.y; \
    f = __half22float2((P)[2]); a2.x += f.x; a2.y += f.y; \
    f = __half22float2((P)[3]); a3.x += f.x; a3.y += f.y; }

#define GATHER_REL(TAB, R, NODE) { \
    int s = g_rowptr[R][NODE], e = g_rowptr[R][NODE + 1]; \
    int k = s + e2; \
    for (; k + 2 < e; k += 4) { \
        int c0 = g_col[R][k], c1 = g_col[R][k + 2]; \
        uint4 v0 = __ldg((TAB) + (size_t)c0 * 16 + ln); \
        uint4 v1 = __ldg((TAB) + (size_t)c1 * 16 + ln); \
        const __half2* p0 = (const __half2*)&v0; \
        const __half2* p1 = (const __half2*)&v1; \
        ACCP(p0); ACCP(p1); \
    } \
    for (; k < e; k += 2) { \
        int c0 = g_col[R][k]; \
        uint4 v0 = __ldg((TAB) + (size_t)c0 * 16 + ln); \
        const __half2* p0 = (const __half2*)&v0; \
        ACCP(p0); \
    } \
}

#define SHFL_COMBINE() { \
    a0.x += __shfl_xor_sync(0xffffffffu, a0.x, 16); \
    a0.y += __shfl_xor_sync(0xffffffffu, a0.y, 16); \
    a1.x += __shfl_xor_sync(0xffffffffu, a1.x, 16); \
    a1.y += __shfl_xor_sync(0xffffffffu, a1.y, 16); \
    a2.x += __shfl_xor_sync(0xffffffffu, a2.x, 16); \
    a2.y += __shfl_xor_sync(0xffffffffu, a2.y, 16); \
    a3.x += __shfl_xor_sync(0xffffffffu, a3.x, 16); \
    a3.y += __shfl_xor_sync(0xffffffffu, a3.y, 16); \
}

// warps [0, NN): router node w  -> out_r = rf + relu(sum A[pass] + sum B[connect] + br)
// warps [NN, 2NN): packet node  -> out_p = pf + relu(mean C[transfer] + bp)
__global__ void k_gather_all(const float* __restrict__ rf, const float* __restrict__ br,
                             const float* __restrict__ pf, const float* __restrict__ bp,
                             float* __restrict__ out) {
    int w = (blockIdx.x * blockDim.x + threadIdx.x) >> 5;
    int lane = threadIdx.x & 31;
    int e2 = lane >> 4, ln = lane & 15;     // lane covers features [ln*8, ln*8+8)

    float2 a0 = {0,0}, a1 = {0,0}, a2 = {0,0}, a3 = {0,0};

    if (w < NN) {
        // router
        const uint4* A = (const uint4*)g_h16[0];
        const uint4* B = (const uint4*)g_h16[1];
        GATHER_REL(A, 0, w);
        GATHER_REL(B, 1, w);
        SHFL_COMBINE();
        if (e2 == 0) {
            float4 b0 = __ldg((const float4*)br + ln * 2);
            float4 b1 = __ldg((const float4*)br + ln * 2 + 1);
            float4 r0 = __ldg((const float4*)(rf + (size_t)w * HH) + ln * 2);
            float4 r1 = __ldg((const float4*)(rf + (size_t)w * HH) + ln * 2 + 1);
            float4 o0, o1;
            o0.x = r0.x + fmaxf(a0.x + b0.x, 0.f);
            o0.y = r0.y + fmaxf(a0.y + b0.y, 0.f);
            o0.z = r0.z + fmaxf(a1.x + b0.z, 0.f);
            o0.w = r0.w + fmaxf(a1.y + b0.w, 0.f);
            o1.x = r1.x + fmaxf(a2.x + b1.x, 0.f);
            o1.y = r1.y + fmaxf(a2.y + b1.y, 0.f);
            o1.z = r1.z + fmaxf(a3.x + b1.z, 0.f);
            o1.w = r1.w + fmaxf(a3.y + b1.w, 0.f);
            ((float4*)(out + (size_t)w * HH))[ln * 2]     = o0;
            ((float4*)(out + (size_t)w * HH))[ln * 2 + 1] = o1;
        }
    } else {
        // packet
        int i = w - NN;
        const uint4* C = (const uint4*)g_h16[2];
        GATHER_REL(C, 2, i);
        SHFL_COMBINE();
        if (e2 == 0) {
            int deg = g_rowptr[2][i + 1] - g_rowptr[2][i];
            float scl = 1.0f / (float)max(deg, 1);
            float4 b0 = __ldg((const float4*)bp + ln * 2);
            float4 b1 = __ldg((const float4*)bp + ln * 2 + 1);
            float4 r0 = __ldg((const float4*)(pf + (size_t)i * HH) + ln * 2);
            float4 r1 = __ldg((const float4*)(pf + (size_t)i * HH) + ln * 2 + 1);
            float4 o0, o1;
            o0.x = r0.x + fmaxf(a0.x * scl + b0.x, 0.f);
            o0.y = r0.y + fmaxf(a0.y * scl + b0.y, 0.f);
            o0.z = r0.z + fmaxf(a1.x * scl + b0.z, 0.f);
            o0.w = r0.w + fmaxf(a1.y * scl + b0.w, 0.f);
            o1.x = r1.x + fmaxf(a2.x * scl + b1.x, 0.f);
            o1.y = r1.y + fmaxf(a2.y * scl + b1.y, 0.f);
            o1.z = r1.z + fmaxf(a3.x * scl + b1.z, 0.f);
            o1.w = r1.w + fmaxf(a3.y * scl + b1.w, 0.f);
            float* outp = out + (size_t)NN * HH;
            ((float4*)(outp + (size_t)i * HH))[ln * 2]     = o0;
            ((float4*)(outp + (size_t)i * HH))[ln * 2 + 1] = o1;
        }
    }
}

// ---------------- launch: concurrent GEMMs on 3 streams, combined gather ----------------
extern "C" void kernel_launch(void* const* d_in, const int* in_sizes, int n_in,
                              void* d_out, int out_size) {
    const float* router_feat  = (const float*)d_in[0];
    const float* packet_feat  = (const float*)d_in[1];
    const float* W_r          = (const float*)d_in[2];
    const float* b_r          = (const float*)d_in[3];
    const float* W_p          = (const float*)d_in[4];
    const float* b_p          = (const float*)d_in[5];
    const int*   pass_src     = (const int*)d_in[6];
    const int*   pass_dst     = (const int*)d_in[7];
    const int*   transfer_src = (const int*)d_in[8];
    const int*   transfer_dst = (const int*)d_in[9];
    const int*   connect_src  = (const int*)d_in[10];
    const int*   connect_dst  = (const int*)d_in[11];
    float* out = (float*)d_out;

    static cudaStream_t s1 = nullptr, s2 = nullptr, s3 = nullptr;
    static cudaEvent_t evFork, evConv, evA, evB, evC;
    static int* degbase = nullptr;
    static __half *hA, *hB, *hC, *hRF, *hPF, *hWR, *hWP;
    if (!s1) {
        cudaStreamCreateWithFlags(&s1, cudaStreamNonBlocking);
        cudaStreamCreateWithFlags(&s2, cudaStreamNonBlocking);
        cudaStreamCreateWithFlags(&s3, cudaStreamNonBlocking);
        cudaEventCreateWithFlags(&evFork, cudaEventDisableTiming);
        cudaEventCreateWithFlags(&evConv, cudaEventDisableTiming);
        cudaEventCreateWithFlags(&evA,    cudaEventDisableTiming);
        cudaEventCreateWithFlags(&evB,    cudaEventDisableTiming);
        cudaEventCreateWithFlags(&evC,    cudaEventDisableTiming);
        cudaGetSymbolAddress((void**)&degbase, g_deg);
        __half* h16base;
        cudaGetSymbolAddress((void**)&h16base, g_h16);
        hA = h16base;
        hB = h16base + (size_t)NN * HH;
        hC = h16base + 2 * (size_t)NN * HH;
        cudaGetSymbolAddress((void**)&hRF, g_rf16);
        cudaGetSymbolAddress((void**)&hPF, g_pf16);
        cudaGetSymbolAddress((void**)&hWR, g_wr16);
        cudaGetSymbolAddress((void**)&hWP, g_wp16);
    }

    // fork
    cudaEventRecord(evFork, 0);
    cudaStreamWaitEvent(s1, evFork, 0);

    // s1: conversions, then the three GEMMs fan out to s1/s2/s3
    k_f16<<<2 * NN * HH / 8 / 256, 256, 0, s1>>>(router_feat, packet_feat);
    k_w16<<<96, 256, 0, s1>>>(W_r, W_p);
    cudaEventRecord(evConv, s1);
    cudaStreamWaitEvent(s2, evConv, 0);
    cudaStreamWaitEvent(s3, evConv, 0);

    k_gemm_h<256, 0  ><<<NN / 128, 256, 0, s1>>>(hPF, hWR, hA);   // A = pf @ Wr[:, :128]^T
    cudaEventRecord(evA, s1);
    k_gemm_h<256, 128><<<NN / 128, 256, 0, s2>>>(hRF, hWR, hB);   // B = rf @ Wr[:, 128:]^T
    cudaEventRecord(evB, s2);
    k_gemm_h<128, 0  ><<<NN / 128, 256, 0, s3>>>(hRF, hWP, hC);   // C = rf @ Wp^T
    cudaEventRecord(evC, s3);

    // s0: CSR build (concurrent with conversions + GEMMs)
    cudaMemsetAsync(degbase, 0, 3 * NN * sizeof(int), 0);
    k_hist<<<(3 * EE / 4 + 255) / 256, 256>>>(pass_dst, connect_dst, transfer_dst);
    k_scan1<<<768, 256>>>();
    k_scan2<<<3, 256>>>();
    k_scan3<<<3 * NN / 256, 256>>>();
    k_fill<<<(3 * EE / 4 + 255) / 256, 256>>>(pass_src, pass_dst, connect_src, connect_dst,
                                              transfer_src, transfer_dst);

    // s0: combined fused gather (needs A, B, C + CSR)
    cudaStreamWaitEvent(0, evA, 0);
    cudaStreamWaitEvent(0, evB, 0);
    cudaStreamWaitEvent(0, evC, 0);
    k_gather_all<<<2 * NN * 32 / 256, 256>>>(router_feat, b_r, packet_feat, b_p, out);
}

// round 11
// speedup vs baseline: 1.0264x; 1.0264x over previous
#include <cuda_runtime.h>
#include <cuda_fp16.h>
#include <cstdint>

#define NN 65536
#define HH 128
#define EE 524288

// ---------------- static scratch ----------------
__device__ int    g_deg[3][NN];
__device__ int    g_rowptr[3][NN + 1];
__device__ int    g_cursor[3][NN];
__device__ int    g_csum[3][256];
__device__ int    g_col[3][EE];
__device__ __half g_h16[3][NN * HH];   // 0: A = pf@Wr1^T, 1: B = rf@Wr2^T, 2: C = rf@Wp^T
__device__ __half g_rf16[NN * HH];
__device__ __half g_pf16[NN * HH];
__device__ __half g_wr16[HH * 256];
__device__ __half g_wp16[HH * HH];

// ---------------- fp16 conversion: feature tables ----------------
__global__ void k_f16(const float* __restrict__ rf, const float* __restrict__ pf) {
    int i = blockIdx.x * blockDim.x + threadIdx.x;   // 8 floats per thread
    const int half_total = NN * HH / 8;
    const float4* src;
    __half* dst;
    int base;
    if (i < half_total) { src = (const float4*)rf; dst = g_rf16; base = i; }
    else                { src = (const float4*)pf; dst = g_pf16; base = i - half_total; }
    float4 v0 = __ldg(src + base * 2);
    float4 v1 = __ldg(src + base * 2 + 1);
    __half2 h[4];
    h[0] = __floats2half2_rn(v0.x, v0.y);
    h[1] = __floats2half2_rn(v0.z, v0.w);
    h[2] = __floats2half2_rn(v1.x, v1.y);
    h[3] = __floats2half2_rn(v1.z, v1.w);
    *(uint4*)(dst + (size_t)base * 8) = *(uint4*)h;
}

// ---------------- fp16 conversion: weights ----------------
__global__ void k_w16(const float* __restrict__ Wr, const float* __restrict__ Wp) {
    int i = blockIdx.x * blockDim.x + threadIdx.x;
    if (i < 16384) {
        float2 v = __ldg((const float2*)Wr + i);
        *(__half2*)(g_wr16 + i * 2) = __floats2half2_rn(v.x, v.y);
    } else if (i < 24576) {
        int j = i - 16384;
        float2 v = __ldg((const float2*)Wp + j);
        *(__half2*)(g_wp16 + j * 2) = __floats2half2_rn(v.x, v.y);
    }
}

// ---------------- CSR build ----------------
__global__ void k_hist(const int* __restrict__ pass_dst,
                       const int* __restrict__ connect_dst,
                       const int* __restrict__ transfer_dst) {
    int q = blockIdx.x * blockDim.x + threadIdx.x;
    if (q >= 3 * EE / 4) return;
    int r = q / (EE / 4), e4 = q - r * (EE / 4);
    const int* dst = (r == 0) ? pass_dst : (r == 1) ? connect_dst : transfer_dst;
    int4 d = __ldg((const int4*)dst + e4);
    atomicAdd(&g_deg[r][d.x], 1);
    atomicAdd(&g_deg[r][d.y], 1);
    atomicAdd(&g_deg[r][d.z], 1);
    atomicAdd(&g_deg[r][d.w], 1);
}

__global__ void k_scan1() {
    int b = blockIdx.x;
    int r = b >> 8, ch = b & 255;
    int t = threadIdx.x;
    int idx = ch * 256 + t;
    int v = g_deg[r][idx];
    __shared__ int sm[256];
    sm[t] = v;
    __syncthreads();
    #pragma unroll
    for (int off = 1; off < 256; off <<= 1) {
        int u = (t >= off) ? sm[t - off] : 0;
        __syncthreads();
        sm[t] += u;
        __syncthreads();
    }
    g_rowptr[r][idx] = sm[t] - v;
    if (t == 255) g_csum[r][ch] = sm[t];
}

__global__ void k_scan2() {
    int r = blockIdx.x;
    int t = threadIdx.x;
    int v = g_csum[r][t];
    __shared__ int sm[256];
    sm[t] = v;
    __syncthreads();
    #pragma unroll
    for (int off = 1; off < 256; off <<= 1) {
        int u = (t >= off) ? sm[t - off] : 0;
        __syncthreads();
        sm[t] += u;
        __syncthreads();
    }
    g_csum[r][t] = sm[t] - v;
    if (t == 255) g_rowptr[r][NN] = sm[t];
}

__global__ void k_scan3() {
    int i = blockIdx.x * blockDim.x + threadIdx.x;
    if (i >= 3 * NN) return;
    int r = i >> 16, n = i & (NN - 1);
    int val = g_rowptr[r][n] + g_csum[r][n >> 8];
    g_rowptr[r][n] = val;
    g_cursor[r][n] = val;
}

__global__ void k_fill(const int* __restrict__ pass_src, const int* __restrict__ pass_dst,
                       const int* __restrict__ connect_src, const int* __restrict__ connect_dst,
                       const int* __restrict__ transfer_src, const int* __restrict__ transfer_dst) {
    int q = blockIdx.x * blockDim.x + threadIdx.x;
    if (q >= 3 * EE / 4) return;
    int r = q / (EE / 4), e4 = q - r * (EE / 4);
    const int *src, *dst;
    if (r == 0)      { src = pass_src;     dst = pass_dst; }
    else if (r == 1) { src = connect_src;  dst = connect_dst; }
    else             { src = transfer_src; dst = transfer_dst; }
    int4 d = __ldg((const int4*)dst + e4);
    int4 s = __ldg((const int4*)src + e4);
    int p0 = atomicAdd(&g_cursor[r][d.x], 1);
    int p1 = atomicAdd(&g_cursor[r][d.y], 1);
    int p2 = atomicAdd(&g_cursor[r][d.z], 1);
    int p3 = atomicAdd(&g_cursor[r][d.w], 1);
    g_col[r][p0] = s.x;
    g_col[r][p1] = s.y;
    g_col[r][p2] = s.z;
    g_col[r][p3] = s.w;
}

// ---------------- fp16 tensor-core plain GEMM ----------------
__device__ __forceinline__ void mma_f16(float* d, const uint32_t* a, const uint32_t* b) {
    asm volatile(
        "mma.sync.aligned.m16n8k16.row.col.f32.f16.f16.f32 "
        "{%0,%1,%2,%3},{%4,%5,%6,%7},{%8,%9},{%0,%1,%2,%3};"
        : "+f"(d[0]), "+f"(d[1]), "+f"(d[2]), "+f"(d[3])
        : "r"(a[0]), "r"(a[1]), "r"(a[2]), "r"(a[3]), "r"(b[0]), "r"(b[1]));
}

#define KC 64
#define XSH 72

template<int LDW, int WOFF>
__global__ void __launch_bounds__(256, 2) k_gemm_h(const __half* __restrict__ X,
                                                   const __half* __restrict__ W,
                                                   __half* __restrict__ Y) {
    __shared__ __half sX[128 * XSH];
    __shared__ __half sW[128 * XSH];

    const int t = threadIdx.x;
    const int warp = t >> 5, lane = t & 31;
    const int g = lane >> 2, tg = lane & 3;
    const int mw = (warp & 3) * 32;
    const int nw = (warp >> 2) * 64;
    const int row0 = blockIdx.x * 128;

    float acc[2][8][4];
    #pragma unroll
    for (int i = 0; i < 2; i++)
        #pragma unroll
        for (int j = 0; j < 8; j++)
            #pragma unroll
            for (int q = 0; q < 4; q++) acc[i][j][q] = 0.f;

    #pragma unroll
    for (int c = 0; c < HH / KC; c++) {
        __syncthreads();
        #pragma unroll
        for (int it = 0; it < 4; it++) {
            int idx = it * 256 + t;
            int row = idx >> 3, c8 = idx & 7;
            uint4 xv = __ldg((const uint4*)(X + (size_t)(row0 + row) * HH + c * KC) + c8);
            *(uint4*)&sX[row * XSH + c8 * 8] = xv;
            uint4 wv = __ldg((const uint4*)(W + (size_t)row * LDW + WOFF + c * KC) + c8);
            *(uint4*)&sW[row * XSH + c8 * 8] = wv;
        }
        __syncthreads();

        #pragma unroll
        for (int ks = 0; ks < KC / 16; ks++) {
            int k0 = ks * 16;
            uint32_t a[2][4], b[8][2];
            #pragma unroll
            for (int i = 0; i < 2; i++) {
                int r = mw + i * 16 + g;
                a[i][0] = *(const uint32_t*)&sX[r * XSH + k0 + 2 * tg];
                a[i][1] = *(const uint32_t*)&sX[(r + 8) * XSH + k0 + 2 * tg];
                a[i][2] = *(const uint32_t*)&sX[r * XSH + k0 + 8 + 2 * tg];
                a[i][3] = *(const uint32_t*)&sX[(r + 8) * XSH + k0 + 8 + 2 * tg];
            }
            #pragma unroll
            for (int j = 0; j < 8; j++) {
                int n = nw + j * 8 + g;
                b[j][0] = *(const uint32_t*)&sW[n * XSH + k0 + 2 * tg];
                b[j][1] = *(const uint32_t*)&sW[n * XSH + k0 + 8 + 2 * tg];
            }
            #pragma unroll
            for (int i = 0; i < 2; i++)
                #pragma unroll
                for (int j = 0; j < 8; j++)
                    mma_f16(acc[i][j], a[i], b[j]);
        }
    }

    #pragma unroll
    for (int j = 0; j < 8; j++) {
        int col = nw + j * 8 + 2 * tg;
        #pragma unroll
        for (int i = 0; i < 2; i++) {
            int ra = row0 + mw + i * 16 + g;
            *(__half2*)(Y + (size_t)ra * HH + col)       = __floats2half2_rn(acc[i][j][0], acc[i][j][1]);
            *(__half2*)(Y + (size_t)(ra + 8) * HH + col) = __floats2half2_rn(acc[i][j][2], acc[i][j][3]);
        }
    }
}

// ---------------- combined fused gather + epilogue (software-pipelined) ----------------
#define ACCP(P) { float2 f; \
    f = __half22float2((P)[0]); a0.x += f.x; a0.y += f.y; \
    f = __half22float2((P)[1]); a1.x += f.x; a1.y += f.y; \
    f = __half22float2((P)[2]); a2.x += f.x; a2.y += f.y; \
    f = __half22float2((P)[3]); a3.x += f.x; a3.y += f.y; }

// 4-deep batched loads: all 4 LDG.128 issue before any accumulate -> 4 row-loads in flight/half-warp
#define GATHER_REL(TAB, R, NODE) { \
    int s = g_rowptr[R][NODE], e = g_rowptr[R][NODE + 1]; \
    int k = s + e2; \
    for (; k + 6 < e; k += 8) { \
        int c0 = g_col[R][k],     c1 = g_col[R][k + 2]; \
        int c2 = g_col[R][k + 4], c3 = g_col[R][k + 6]; \
        uint4 v0 = __ldg((TAB) + (size_t)c0 * 16 + ln); \
        uint4 v1 = __ldg((TAB) + (size_t)c1 * 16 + ln); \
        uint4 v2 = __ldg((TAB) + (size_t)c2 * 16 + ln); \
        uint4 v3 = __ldg((TAB) + (size_t)c3 * 16 + ln); \
        const __half2* p0 = (const __half2*)&v0; \
        const __half2* p1 = (const __half2*)&v1; \
        const __half2* p2 = (const __half2*)&v2; \
        const __half2* p3 = (const __half2*)&v3; \
        ACCP(p0); ACCP(p1); ACCP(p2); ACCP(p3); \
    } \
    if (k + 2 < e) { \
        int c0 = g_col[R][k], c1 = g_col[R][k + 2]; \
        uint4 v0 = __ldg((TAB) + (size_t)c0 * 16 + ln); \
        uint4 v1 = __ldg((TAB) + (size_t)c1 * 16 + ln); \
        const __half2* p0 = (const __half2*)&v0; \
        const __half2* p1 = (const __half2*)&v1; \
        ACCP(p0); ACCP(p1); \
        k += 4; \
    } \
    if (k < e) { \
        int c0 = g_col[R][k]; \
        uint4 v0 = __ldg((TAB) + (size_t)c0 * 16 + ln); \
        const __half2* p0 = (const __half2*)&v0; \
        ACCP(p0); \
    } \
}

#define SHFL_COMBINE() { \
    a0.x += __shfl_xor_sync(0xffffffffu, a0.x, 16); \
    a0.y += __shfl_xor_sync(0xffffffffu, a0.y, 16); \
    a1.x += __shfl_xor_sync(0xffffffffu, a1.x, 16); \
    a1.y += __shfl_xor_sync(0xffffffffu, a1.y, 16); \
    a2.x += __shfl_xor_sync(0xffffffffu, a2.x, 16); \
    a2.y += __shfl_xor_sync(0xffffffffu, a2.y, 16); \
    a3.x += __shfl_xor_sync(0xffffffffu, a3.x, 16); \
    a3.y += __shfl_xor_sync(0xffffffffu, a3.y, 16); \
}

// warps [0, NN): router node w  -> out_r = rf + relu(sum A[pass] + sum B[connect] + br)
// warps [NN, 2NN): packet node  -> out_p = pf + relu(mean C[transfer] + bp)
__global__ void k_gather_all(const float* __restrict__ rf, const float* __restrict__ br,
                             const float* __restrict__ pf, const float* __restrict__ bp,
                             float* __restrict__ out) {
    int w = (blockIdx.x * blockDim.x + threadIdx.x) >> 5;
    int lane = threadIdx.x & 31;
    int e2 = lane >> 4, ln = lane & 15;     // lane covers features [ln*8, ln*8+8)

    float2 a0 = {0,0}, a1 = {0,0}, a2 = {0,0}, a3 = {0,0};

    if (w < NN) {
        // router
        const uint4* A = (const uint4*)g_h16[0];
        const uint4* B = (const uint4*)g_h16[1];
        GATHER_REL(A, 0, w);
        GATHER_REL(B, 1, w);
        SHFL_COMBINE();
        if (e2 == 0) {
            float4 b0 = __ldg((const float4*)br + ln * 2);
            float4 b1 = __ldg((const float4*)br + ln * 2 + 1);
            float4 r0 = __ldg((const float4*)(rf + (size_t)w * HH) + ln * 2);
            float4 r1 = __ldg((const float4*)(rf + (size_t)w * HH) + ln * 2 + 1);
            float4 o0, o1;
            o0.x = r0.x + fmaxf(a0.x + b0.x, 0.f);
            o0.y = r0.y + fmaxf(a0.y + b0.y, 0.f);
            o0.z = r0.z + fmaxf(a1.x + b0.z, 0.f);
            o0.w = r0.w + fmaxf(a1.y + b0.w, 0.f);
            o1.x = r1.x + fmaxf(a2.x + b1.x, 0.f);
            o1.y = r1.y + fmaxf(a2.y + b1.y, 0.f);
            o1.z = r1.z + fmaxf(a3.x + b1.z, 0.f);
            o1.w = r1.w + fmaxf(a3.y + b1.w, 0.f);
            ((float4*)(out + (size_t)w * HH))[ln * 2]     = o0;
            ((float4*)(out + (size_t)w * HH))[ln * 2 + 1] = o1;
        }
    } else {
        // packet
        int i = w - NN;
        const uint4* C = (const uint4*)g_h16[2];
        GATHER_REL(C, 2, i);
        SHFL_COMBINE();
        if (e2 == 0) {
            int deg = g_rowptr[2][i + 1] - g_rowptr[2][i];
            float scl = 1.0f / (float)max(deg, 1);
            float4 b0 = __ldg((const float4*)bp + ln * 2);
            float4 b1 = __ldg((const float4*)bp + ln * 2 + 1);
            float4 r0 = __ldg((const float4*)(pf + (size_t)i * HH) + ln * 2);
            float4 r1 = __ldg((const float4*)(pf + (size_t)i * HH) + ln * 2 + 1);
            float4 o0, o1;
            o0.x = r0.x + fmaxf(a0.x * scl + b0.x, 0.f);
            o0.y = r0.y + fmaxf(a0.y * scl + b0.y, 0.f);
            o0.z = r0.z + fmaxf(a1.x * scl + b0.z, 0.f);
            o0.w = r0.w + fmaxf(a1.y * scl + b0.w, 0.f);
            o1.x = r1.x + fmaxf(a2.x * scl + b1.x, 0.f);
            o1.y = r1.y + fmaxf(a2.y * scl + b1.y, 0.f);
            o1.z = r1.z + fmaxf(a3.x * scl + b1.z, 0.f);
            o1.w = r1.w + fmaxf(a3.y * scl + b1.w, 0.f);
            float* outp = out + (size_t)NN * HH;
            ((float4*)(outp + (size_t)i * HH))[ln * 2]     = o0;
            ((float4*)(outp + (size_t)i * HH))[ln * 2 + 1] = o1;
        }
    }
}

// ---------------- launch: concurrent GEMMs on 3 streams, combined gather ----------------
extern "C" void kernel_launch(void* const* d_in, const int* in_sizes, int n_in,
                              void* d_out, int out_size) {
    const float* router_feat  = (const float*)d_in[0];
    const float* packet_feat  = (const float*)d_in[1];
    const float* W_r          = (const float*)d_in[2];
    const float* b_r          = (const float*)d_in[3];
    const float* W_p          = (const float*)d_in[4];
    const float* b_p          = (const float*)d_in[5];
    const int*   pass_src     = (const int*)d_in[6];
    const int*   pass_dst     = (const int*)d_in[7];
    const int*   transfer_src = (const int*)d_in[8];
    const int*   transfer_dst = (const int*)d_in[9];
    const int*   connect_src  = (const int*)d_in[10];
    const int*   connect_dst  = (const int*)d_in[11];
    float* out = (float*)d_out;

    static cudaStream_t s1 = nullptr, s2 = nullptr, s3 = nullptr;
    static cudaEvent_t evFork, evConv, evA, evB, evC;
    static int* degbase = nullptr;
    static __half *hA, *hB, *hC, *hRF, *hPF, *hWR, *hWP;
    if (!s1) {
        cudaStreamCreateWithFlags(&s1, cudaStreamNonBlocking);
        cudaStreamCreateWithFlags(&s2, cudaStreamNonBlocking);
        cudaStreamCreateWithFlags(&s3, cudaStreamNonBlocking);
        cudaEventCreateWithFlags(&evFork, cudaEventDisableTiming);
        cudaEventCreateWithFlags(&evConv, cudaEventDisableTiming);
        cudaEventCreateWithFlags(&evA,    cudaEventDisableTiming);
        cudaEventCreateWithFlags(&evB,    cudaEventDisableTiming);
        cudaEventCreateWithFlags(&evC,    cudaEventDisableTiming);
        cudaGetSymbolAddress((void**)&degbase, g_deg);
        __half* h16base;
        cudaGetSymbolAddress((void**)&h16base, g_h16);
        hA = h16base;
        hB = h16base + (size_t)NN * HH;
        hC = h16base + 2 * (size_t)NN * HH;
        cudaGetSymbolAddress((void**)&hRF, g_rf16);
        cudaGetSymbolAddress((void**)&hPF, g_pf16);
        cudaGetSymbolAddress((void**)&hWR, g_wr16);
        cudaGetSymbolAddress((void**)&hWP, g_wp16);
    }

    // fork
    cudaEventRecord(evFork, 0);
    cudaStreamWaitEvent(s1, evFork, 0);

    // s1: conversions, then the three GEMMs fan out to s1/s2/s3
    k_f16<<<2 * NN * HH / 8 / 256, 256, 0, s1>>>(router_feat, packet_feat);
    k_w16<<<96, 256, 0, s1>>>(W_r, W_p);
    cudaEventRecord(evConv, s1);
    cudaStreamWaitEvent(s2, evConv, 0);
    cudaStreamWaitEvent(s3, evConv, 0);

    k_gemm_h<256, 0  ><<<NN / 128, 256, 0, s1>>>(hPF, hWR, hA);   // A = pf @ Wr[:, :128]^T
    cudaEventRecord(evA, s1);
    k_gemm_h<256, 128><<<NN / 128, 256, 0, s2>>>(hRF, hWR, hB);   // B = rf @ Wr[:, 128:]^T
    cudaEventRecord(evB, s2);
    k_gemm_h<128, 0  ><<<NN / 128, 256, 0, s3>>>(hRF, hWP, hC);   // C = rf @ Wp^T
    cudaEventRecord(evC, s3);

    // s0: CSR build (concurrent with conversions + GEMMs)
    cudaMemsetAsync(degbase, 0, 3 * NN * sizeof(int), 0);
    k_hist<<<(3 * EE / 4 + 255) / 256, 256>>>(pass_dst, connect_dst, transfer_dst);
    k_scan1<<<768, 256>>>();
    k_scan2<<<3, 256>>>();
    k_scan3<<<3 * NN / 256, 256>>>();
    k_fill<<<(3 * EE / 4 + 255) / 256, 256>>>(pass_src, pass_dst, connect_src, connect_dst,
                                              transfer_src, transfer_dst);

    // s0: combined fused gather (needs A, B, C + CSR)
    cudaStreamWaitEvent(0, evA, 0);
    cudaStreamWaitEvent(0, evB, 0);
    cudaStreamWaitEvent(0, evC, 0);
    k_gather_all<<<2 * NN * 32 / 256, 256>>>(router_feat, b_r, packet_feat, b_p, out);
}

// round 12
// speedup vs baseline: 1.0744x; 1.0468x over previous
#include <cuda_runtime.h>
#include <cuda_fp16.h>
#include <cstdint>

#define NN 65536
#define HH 128
#define EE 524288

// ---------------- static scratch ----------------
__device__ int    g_deg[3][NN];
__device__ int    g_rowptr[3][NN + 1];
__device__ int    g_cursor[3][NN];
__device__ int    g_csum[3][256];
__device__ int    g_col[3][EE];
__device__ __half g_h16[3][NN * HH];   // 0: A = pf@Wr1^T, 1: B = rf@Wr2^T, 2: C = rf@Wp^T

// ---------------- CSR build ----------------
__global__ void k_hist(const int* __restrict__ pass_dst,
                       const int* __restrict__ connect_dst,
                       const int* __restrict__ transfer_dst) {
    int q = blockIdx.x * blockDim.x + threadIdx.x;
    if (q >= 3 * EE / 4) return;
    int r = q / (EE / 4), e4 = q - r * (EE / 4);
    const int* dst = (r == 0) ? pass_dst : (r == 1) ? connect_dst : transfer_dst;
    int4 d = __ldg((const int4*)dst + e4);
    atomicAdd(&g_deg[r][d.x], 1);
    atomicAdd(&g_deg[r][d.y], 1);
    atomicAdd(&g_deg[r][d.z], 1);
    atomicAdd(&g_deg[r][d.w], 1);
}

__global__ void k_scan1() {
    int b = blockIdx.x;
    int r = b >> 8, ch = b & 255;
    int t = threadIdx.x;
    int idx = ch * 256 + t;
    int v = g_deg[r][idx];
    __shared__ int sm[256];
    sm[t] = v;
    __syncthreads();
    #pragma unroll
    for (int off = 1; off < 256; off <<= 1) {
        int u = (t >= off) ? sm[t - off] : 0;
        __syncthreads();
        sm[t] += u;
        __syncthreads();
    }
    g_rowptr[r][idx] = sm[t] - v;
    if (t == 255) g_csum[r][ch] = sm[t];
}

__global__ void k_scan2() {
    int r = blockIdx.x;
    int t = threadIdx.x;
    int v = g_csum[r][t];
    __shared__ int sm[256];
    sm[t] = v;
    __syncthreads();
    #pragma unroll
    for (int off = 1; off < 256; off <<= 1) {
        int u = (t >= off) ? sm[t - off] : 0;
        __syncthreads();
        sm[t] += u;
        __syncthreads();
    }
    g_csum[r][t] = sm[t] - v;
    if (t == 255) g_rowptr[r][NN] = sm[t];
}

__global__ void k_scan3() {
    int i = blockIdx.x * blockDim.x + threadIdx.x;
    if (i >= 3 * NN) return;
    int r = i >> 16, n = i & (NN - 1);
    int val = g_rowptr[r][n] + g_csum[r][n >> 8];
    g_rowptr[r][n] = val;
    g_cursor[r][n] = val;
}

__global__ void k_fill(const int* __restrict__ pass_src, const int* __restrict__ pass_dst,
                       const int* __restrict__ connect_src, const int* __restrict__ connect_dst,
                       const int* __restrict__ transfer_src, const int* __restrict__ transfer_dst) {
    int q = blockIdx.x * blockDim.x + threadIdx.x;
    if (q >= 3 * EE / 4) return;
    int r = q / (EE / 4), e4 = q - r * (EE / 4);
    const int *src, *dst;
    if (r == 0)      { src = pass_src;     dst = pass_dst; }
    else if (r == 1) { src = connect_src;  dst = connect_dst; }
    else             { src = transfer_src; dst = transfer_dst; }
    int4 d = __ldg((const int4*)dst + e4);
    int4 s = __ldg((const int4*)src + e4);
    int p0 = atomicAdd(&g_cursor[r][d.x], 1);
    int p1 = atomicAdd(&g_cursor[r][d.y], 1);
    int p2 = atomicAdd(&g_cursor[r][d.z], 1);
    int p3 = atomicAdd(&g_cursor[r][d.w], 1);
    g_col[r][p0] = s.x;
    g_col[r][p1] = s.y;
    g_col[r][p2] = s.z;
    g_col[r][p3] = s.w;
}

// ---------------- merged fp16 tensor-core GEMM (fp32 in, convert at smem store) ----------------
__device__ __forceinline__ void mma_f16(float* d, const uint32_t* a, const uint32_t* b) {
    asm volatile(
        "mma.sync.aligned.m16n8k16.row.col.f32.f16.f16.f32 "
        "{%0,%1,%2,%3},{%4,%5,%6,%7},{%8,%9},{%0,%1,%2,%3};"
        : "+f"(d[0]), "+f"(d[1]), "+f"(d[2]), "+f"(d[3])
        : "r"(a[0]), "r"(a[1]), "r"(a[2]), "r"(a[3]), "r"(b[0]), "r"(b[1]));
}

__device__ __forceinline__ void ldm_x4(uint32_t* r, uint32_t addr) {
    asm volatile("ldmatrix.sync.aligned.m8n8.x4.shared.b16 {%0,%1,%2,%3}, [%4];"
        : "=r"(r[0]), "=r"(r[1]), "=r"(r[2]), "=r"(r[3]) : "r"(addr));
}

#define XSH 136   // padded smem stride in halves (272B rows; 272 mod 128 = 16 -> ldmatrix conflict-free)
#define GEMM_SMEM (2 * 128 * XSH * 2)

// blocks [0,512): A = pf @ Wr[:, :128]^T ; [512,1024): B = rf @ Wr[:,128:]^T ; [1024,1536): C = rf @ Wp^T
__global__ void __launch_bounds__(256, 2) k_gemm_all(const float* __restrict__ rf,
                                                     const float* __restrict__ pf,
                                                     const float* __restrict__ Wr,
                                                     const float* __restrict__ Wp) {
    extern __shared__ __half smem[];
    __half* sX = smem;
    __half* sW = smem + 128 * XSH;

    const int b = blockIdx.x;
    const int gid = b >> 9;
    const int tile = b & 511;
    const float* X;
    const float* W;
    int ldw, woff;
    if (gid == 0)      { X = pf; W = Wr; ldw = 256; woff = 0; }
    else if (gid == 1) { X = rf; W = Wr; ldw = 256; woff = 128; }
    else               { X = rf; W = Wp; ldw = 128; woff = 0; }
    __half* Y = g_h16[gid];

    const int t = threadIdx.x;
    const int warp = t >> 5, lane = t & 31;
    const int g = lane >> 2, tg = lane & 3;
    const int mw = (warp & 3) * 32;
    const int nw = (warp >> 2) * 64;
    const int row0 = tile * 128;

    // ---- load X,W tiles (fp32 -> fp16 at store) ----
    #pragma unroll
    for (int it = 0; it < 16; it++) {
        int idx = it * 256 + t;             // 4096 float4 slots each
        int row = idx >> 5, c4 = idx & 31;
        float4 xv = __ldg((const float4*)(X + (size_t)(row0 + row) * HH) + c4);
        __half2 x0 = __floats2half2_rn(xv.x, xv.y);
        __half2 x1 = __floats2half2_rn(xv.z, xv.w);
        *(uint2*)&sX[row * XSH + c4 * 4] = make_uint2(*(uint32_t*)&x0, *(uint32_t*)&x1);
        float4 wv = __ldg((const float4*)(W + (size_t)row * ldw + woff) + c4);
        __half2 w0 = __floats2half2_rn(wv.x, wv.y);
        __half2 w1 = __floats2half2_rn(wv.z, wv.w);
        *(uint2*)&sW[row * XSH + c4 * 4] = make_uint2(*(uint32_t*)&w0, *(uint32_t*)&w1);
    }
    __syncthreads();

    // ---- precompute ldmatrix addresses ----
    uint32_t sXa = (uint32_t)__cvta_generic_to_shared(sX);
    uint32_t sWa = (uint32_t)__cvta_generic_to_shared(sW);
    const int l = lane;
    uint32_t aA0 = sXa + (uint32_t)(((mw + (l & 15)) * XSH + ((l >> 4) * 8)) * 2);
    uint32_t aA1 = aA0 + 16 * XSH * 2;
    uint32_t aB0 = sWa + (uint32_t)(((nw + (l & 7) + ((l >> 4) & 1) * 8) * XSH + (((l >> 3) & 1) * 8)) * 2);

    float acc[2][8][4];
    #pragma unroll
    for (int i = 0; i < 2; i++)
        #pragma unroll
        for (int j = 0; j < 8; j++)
            #pragma unroll
            for (int q = 0; q < 4; q++) acc[i][j][q] = 0.f;

    // ---- mainloop: K=128 in 8 steps of k16; 6 ldmatrix.x4 + 16 MMA per step ----
    #pragma unroll
    for (int ks = 0; ks < 8; ks++) {
        uint32_t koff = ks * 32;   // 16 halves = 32 bytes
        uint32_t a[2][4];
        ldm_x4(a[0], aA0 + koff);
        ldm_x4(a[1], aA1 + koff);
        uint32_t bb[16];           // bb[jp*4 + {0,1,2,3}] = b[2jp][0], b[2jp][1], b[2jp+1][0], b[2jp+1][1]
        #pragma unroll
        for (int jp = 0; jp < 4; jp++)
            ldm_x4(&bb[jp * 4], aB0 + jp * (16 * XSH * 2) + koff);
        #pragma unroll
        for (int i = 0; i < 2; i++)
            #pragma unroll
            for (int j = 0; j < 8; j++)
                mma_f16(acc[i][j], a[i], &bb[(j >> 1) * 4 + (j & 1) * 2]);
    }

    // ---- epilogue: fp16 store ----
    #pragma unroll
    for (int j = 0; j < 8; j++) {
        int col = nw + j * 8 + 2 * tg;
        #pragma unroll
        for (int i = 0; i < 2; i++) {
            int ra = row0 + mw + i * 16 + g;
            *(__half2*)(Y + (size_t)ra * HH + col)       = __floats2half2_rn(acc[i][j][0], acc[i][j][1]);
            *(__half2*)(Y + (size_t)(ra + 8) * HH + col) = __floats2half2_rn(acc[i][j][2], acc[i][j][3]);
        }
    }
}

// ---------------- combined fused gather + epilogue (software-pipelined) ----------------
#define ACCP(P) { float2 f; \
    f = __half22float2((P)[0]); a0.x += f.x; a0.y += f.y; \
    f = __half22float2((P)[1]); a1.x += f.x; a1.y += f.y; \
    f = __half22float2((P)[2]); a2.x += f.x; a2.y += f.y; \
    f = __half22float2((P)[3]); a3.x += f.x; a3.y += f.y; }

#define GATHER_REL(TAB, R, NODE) { \
    int s = g_rowptr[R][NODE], e = g_rowptr[R][NODE + 1]; \
    int k = s + e2; \
    for (; k + 6 < e; k += 8) { \
        int c0 = g_col[R][k],     c1 = g_col[R][k + 2]; \
        int c2 = g_col[R][k + 4], c3 = g_col[R][k + 6]; \
        uint4 v0 = __ldg((TAB) + (size_t)c0 * 16 + ln); \
        uint4 v1 = __ldg((TAB) + (size_t)c1 * 16 + ln); \
        uint4 v2 = __ldg((TAB) + (size_t)c2 * 16 + ln); \
        uint4 v3 = __ldg((TAB) + (size_t)c3 * 16 + ln); \
        const __half2* p0 = (const __half2*)&v0; \
        const __half2* p1 = (const __half2*)&v1; \
        const __half2* p2 = (const __half2*)&v2; \
        const __half2* p3 = (const __half2*)&v3; \
        ACCP(p0); ACCP(p1); ACCP(p2); ACCP(p3); \
    } \
    if (k + 2 < e) { \
        int c0 = g_col[R][k], c1 = g_col[R][k + 2]; \
        uint4 v0 = __ldg((TAB) + (size_t)c0 * 16 + ln); \
        uint4 v1 = __ldg((TAB) + (size_t)c1 * 16 + ln); \
        const __half2* p0 = (const __half2*)&v0; \
        const __half2* p1 = (const __half2*)&v1; \
        ACCP(p0); ACCP(p1); \
        k += 4; \
    } \
    if (k < e) { \
        int c0 = g_col[R][k]; \
        uint4 v0 = __ldg((TAB) + (size_t)c0 * 16 + ln); \
        const __half2* p0 = (const __half2*)&v0; \
        ACCP(p0); \
    } \
}

#define SHFL_COMBINE() { \
    a0.x += __shfl_xor_sync(0xffffffffu, a0.x, 16); \
    a0.y += __shfl_xor_sync(0xffffffffu, a0.y, 16); \
    a1.x += __shfl_xor_sync(0xffffffffu, a1.x, 16); \
    a1.y += __shfl_xor_sync(0xffffffffu, a1.y, 16); \
    a2.x += __shfl_xor_sync(0xffffffffu, a2.x, 16); \
    a2.y += __shfl_xor_sync(0xffffffffu, a2.y, 16); \
    a3.x += __shfl_xor_sync(0xffffffffu, a3.x, 16); \
    a3.y += __shfl_xor_sync(0xffffffffu, a3.y, 16); \
}

__global__ void k_gather_all(const float* __restrict__ rf, const float* __restrict__ br,
                             const float* __restrict__ pf, const float* __restrict__ bp,
                             float* __restrict__ out) {
    int w = (blockIdx.x * blockDim.x + threadIdx.x) >> 5;
    int lane = threadIdx.x & 31;
    int e2 = lane >> 4, ln = lane & 15;

    float2 a0 = {0,0}, a1 = {0,0}, a2 = {0,0}, a3 = {0,0};

    if (w < NN) {
        const uint4* A = (const uint4*)g_h16[0];
        const uint4* B = (const uint4*)g_h16[1];
        GATHER_REL(A, 0, w);
        GATHER_REL(B, 1, w);
        SHFL_COMBINE();
        if (e2 == 0) {
            float4 b0 = __ldg((const float4*)br + ln * 2);
            float4 b1 = __ldg((const float4*)br + ln * 2 + 1);
            float4 r0 = __ldg((const float4*)(rf + (size_t)w * HH) + ln * 2);
            float4 r1 = __ldg((const float4*)(rf + (size_t)w * HH) + ln * 2 + 1);
            float4 o0, o1;
            o0.x = r0.x + fmaxf(a0.x + b0.x, 0.f);
            o0.y = r0.y + fmaxf(a0.y + b0.y, 0.f);
            o0.z = r0.z + fmaxf(a1.x + b0.z, 0.f);
            o0.w = r0.w + fmaxf(a1.y + b0.w, 0.f);
            o1.x = r1.x + fmaxf(a2.x + b1.x, 0.f);
            o1.y = r1.y + fmaxf(a2.y + b1.y, 0.f);
            o1.z = r1.z + fmaxf(a3.x + b1.z, 0.f);
            o1.w = r1.w + fmaxf(a3.y + b1.w, 0.f);
            ((float4*)(out + (size_t)w * HH))[ln * 2]     = o0;
            ((float4*)(out + (size_t)w * HH))[ln * 2 + 1] = o1;
        }
    } else {
        int i = w - NN;
        const uint4* C = (const uint4*)g_h16[2];
        GATHER_REL(C, 2, i);
        SHFL_COMBINE();
        if (e2 == 0) {
            int deg = g_rowptr[2][i + 1] - g_rowptr[2][i];
            float scl = 1.0f / (float)max(deg, 1);
            float4 b0 = __ldg((const float4*)bp + ln * 2);
            float4 b1 = __ldg((const float4*)bp + ln * 2 + 1);
            float4 r0 = __ldg((const float4*)(pf + (size_t)i * HH) + ln * 2);
            float4 r1 = __ldg((const float4*)(pf + (size_t)i * HH) + ln * 2 + 1);
            float4 o0, o1;
            o0.x = r0.x + fmaxf(a0.x * scl + b0.x, 0.f);
            o0.y = r0.y + fmaxf(a0.y * scl + b0.y, 0.f);
            o0.z = r0.z + fmaxf(a1.x * scl + b0.z, 0.f);
            o0.w = r0.w + fmaxf(a1.y * scl + b0.w, 0.f);
            o1.x = r1.x + fmaxf(a2.x * scl + b1.x, 0.f);
            o1.y = r1.y + fmaxf(a2.y * scl + b1.y, 0.f);
            o1.z = r1.z + fmaxf(a3.x * scl + b1.z, 0.f);
            o1.w = r1.w + fmaxf(a3.y * scl + b1.w, 0.f);
            float* outp = out + (size_t)NN * HH;
            ((float4*)(outp + (size_t)i * HH))[ln * 2]     = o0;
            ((float4*)(outp + (size_t)i * HH))[ln * 2 + 1] = o1;
        }
    }
}

// ---------------- launch ----------------
extern "C" void kernel_launch(void* const* d_in, const int* in_sizes, int n_in,
                              void* d_out, int out_size) {
    const float* router_feat  = (const float*)d_in[0];
    const float* packet_feat  = (const float*)d_in[1];
    const float* W_r          = (const float*)d_in[2];
    const float* b_r          = (const float*)d_in[3];
    const float* W_p          = (const float*)d_in[4];
    const float* b_p          = (const float*)d_in[5];
    const int*   pass_src     = (const int*)d_in[6];
    const int*   pass_dst     = (const int*)d_in[7];
    const int*   transfer_src = (const int*)d_in[8];
    const int*   transfer_dst = (const int*)d_in[9];
    const int*   connect_src  = (const int*)d_in[10];
    const int*   connect_dst  = (const int*)d_in[11];
    float* out = (float*)d_out;

    static cudaStream_t s1 = nullptr;
    static cudaEvent_t evFork, evG, evJoin;
    static int* degbase = nullptr;
    if (!s1) {
        cudaStreamCreateWithFlags(&s1, cudaStreamNonBlocking);
        cudaEventCreateWithFlags(&evFork, cudaEventDisableTiming);
        cudaEventCreateWithFlags(&evG,    cudaEventDisableTiming);
        cudaEventCreateWithFlags(&evJoin, cudaEventDisableTiming);
        cudaGetSymbolAddress((void**)&degbase, g_deg);
        cudaFuncSetAttribute(k_gemm_all, cudaFuncAttributeMaxDynamicSharedMemorySize, GEMM_SMEM);
    }

    // fork
    cudaEventRecord(evFork, 0);
    cudaStreamWaitEvent(s1, evFork, 0);

    // s1: merged GEMM (no dependencies — starts at t=0)
    k_gemm_all<<<1536, 256, GEMM_SMEM, s1>>>(router_feat, packet_feat, W_r, W_p);
    cudaEventRecord(evG, s1);

    // s0: CSR build (concurrent)
    cudaMemsetAsync(degbase, 0, 3 * NN * sizeof(int), 0);
    k_hist<<<(3 * EE / 4 + 255) / 256, 256>>>(pass_dst, connect_dst, transfer_dst);
    k_scan1<<<768, 256>>>();
    k_scan2<<<3, 256>>>();
    k_scan3<<<3 * NN / 256, 256>>>();
    k_fill<<<(3 * EE / 4 + 255) / 256, 256>>>(pass_src, pass_dst, connect_src, connect_dst,
                                              transfer_src, transfer_dst);

    // s0: combined fused gather (needs GEMM outputs + CSR)
    cudaStreamWaitEvent(0, evG, 0);
    k_gather_all<<<2 * NN * 32 / 256, 256>>>(router_feat, b_r, packet_feat, b_p, out);
}